// round 3
// baseline (speedup 1.0000x reference)
#include <cuda_runtime.h>
#include <cuda_bf16.h>
#include <math.h>
#include <float.h>

// Problem shape (LG_MGC_2731599200834): B=256, L=576, D=1024, k=24
#define D_DIM 1024
#define MAX_B 256
#define MAX_L 576
#define MAX_K 64
#define DSPLIT 4                       // gather kernel splits D into 4 chunks

// Scratch (device globals; no allocation allowed).
__device__ float g_sims[MAX_B * MAX_L];     // ranking scores
__device__ int   g_topk[MAX_B * MAX_K];     // selected token indices per batch

// ---------------------------------------------------------------------------
// Kernel A: one streaming pass over image_feats (604 MB) — DRAM-bound.
// grid = (ceil(L/8), B), block = 256 (8 warps). One warp per token.
// Ranking by dot * rsqrt(|t|^2) is order-equivalent to the reference cosine
// (n_i is a positive per-batch scalar; eps clamp inactive at these scales).
// ---------------------------------------------------------------------------
__global__ void __launch_bounds__(256)
sims_kernel(const float* __restrict__ i_feats,
            const float* __restrict__ image_feats,
            int L)
{
    __shared__ float4 s_i[D_DIM / 4];   // 4 KB: i_feats row for this batch

    const int b    = blockIdx.y;
    const int tid  = threadIdx.x;
    const int warp = tid >> 5;
    const int lane = tid & 31;

    s_i[tid] = reinterpret_cast<const float4*>(i_feats + (size_t)b * D_DIM)[tid];
    __syncthreads();

    const int token = blockIdx.x * 8 + warp;
    if (token >= L) return;

    const float4* __restrict__ tok = reinterpret_cast<const float4*>(
        image_feats + ((size_t)b * L + token) * D_DIM) + lane;

    float dot = 0.f, nt2 = 0.f;
    #pragma unroll
    for (int j = 0; j < D_DIM / (32 * 4); ++j) {      // 8 iterations
        float4 v = __ldg(tok + j * 32);               // coalesced 128B/warp/step
        float4 a = s_i[lane + j * 32];
        dot += a.x * v.x + a.y * v.y + a.z * v.z + a.w * v.w;
        nt2 += v.x * v.x + v.y * v.y + v.z * v.z + v.w * v.w;
    }

    #pragma unroll
    for (int off = 16; off > 0; off >>= 1) {
        dot += __shfl_xor_sync(0xffffffffu, dot, off);
        nt2 += __shfl_xor_sync(0xffffffffu, nt2, off);
    }

    if (lane == 0)
        g_sims[b * L + token] = dot * rsqrtf(fmaxf(nt2, 1e-16f));
}

// ---------------------------------------------------------------------------
// Kernel S: parallel rank-based bottom-k selection.
// grid = B, block = L (576 = 18 warps). Thread i owns element i:
//   rank(i) = #{ j : v_j < v_i  ||  (v_j == v_i && j < i) }
// rank < k  <=>  element i is among the k smallest (stable tie-break, same
// set as jax top_k of negated sims). Selected threads write their index to
// slot `rank` — a collision-free compaction.
// The scan loop uses a uniform j, so every LDS is a broadcast (conflict-free).
// ---------------------------------------------------------------------------
__global__ void __launch_bounds__(MAX_L)
select_kernel(const int* __restrict__ k_ptr, int L)
{
    __shared__ float s_v[MAX_L];

    const int b = blockIdx.x;
    const int i = threadIdx.x;

    int k = *k_ptr;
    if (k < 1) k = 1;
    if (k > MAX_K) k = MAX_K;

    float v = g_sims[b * L + i];
    s_v[i] = v;
    __syncthreads();

    int rank = 0;
    #pragma unroll 8
    for (int j = 0; j < MAX_L; ++j) {
        float w = s_v[j];                 // broadcast read
        rank += (w < v) | ((w == v) & (j < i));
    }

    if (rank < k)
        g_topk[b * MAX_K + rank] = i;
}

// ---------------------------------------------------------------------------
// Kernel G: split gather-mean.
// grid = (DSPLIT, B), block = 64 threads. Thread t owns one float4 of the
// D/DSPLIT = 256-dim chunk. k independent float4 loads per thread (MLP=24),
// each warp's load is a contiguous 1 KB burst within a token row.
// ---------------------------------------------------------------------------
__global__ void __launch_bounds__(64)
gather_mean_kernel(const float* __restrict__ image_feats,
                   const int* __restrict__ k_ptr,
                   float* __restrict__ out,
                   int L)
{
    __shared__ int s_idx[MAX_K];

    const int split = blockIdx.x;
    const int b     = blockIdx.y;
    const int tid   = threadIdx.x;

    int k = *k_ptr;
    if (k < 1) k = 1;
    if (k > MAX_K) k = MAX_K;

    if (tid < k)
        s_idx[tid] = g_topk[b * MAX_K + tid];
    __syncthreads();

    const int fvec = split * 64 + tid;       // float4 index within the row
    const float4* base = reinterpret_cast<const float4*>(
        image_feats + (size_t)b * L * D_DIM) + fvec;

    float4 acc = make_float4(0.f, 0.f, 0.f, 0.f);
    #pragma unroll 8
    for (int j = 0; j < k; ++j) {
        float4 v = __ldg(base + (size_t)s_idx[j] * (D_DIM / 4));
        acc.x += v.x; acc.y += v.y; acc.z += v.z; acc.w += v.w;
    }
    const float inv_k = 1.0f / (float)k;
    acc.x *= inv_k; acc.y *= inv_k; acc.z *= inv_k; acc.w *= inv_k;
    reinterpret_cast<float4*>(out + (size_t)b * D_DIM)[fvec] = acc;
}

// ---------------------------------------------------------------------------
extern "C" void kernel_launch(void* const* d_in, const int* in_sizes, int n_in,
                              void* d_out, int out_size)
{
    const float* i_feats     = (const float*)d_in[0];   // [B, D]
    const float* image_feats = (const float*)d_in[1];   // [B, L, D]
    const int*   k_ptr       = (const int*)d_in[2];     // scalar k

    const int B = in_sizes[0] / D_DIM;                  // 256
    const int L = in_sizes[1] / in_sizes[0];            // 576

    dim3 gridA((L + 7) / 8, B);
    sims_kernel<<<gridA, 256>>>(i_feats, image_feats, L);

    select_kernel<<<B, L>>>(k_ptr, L);

    dim3 gridG(DSPLIT, B);
    gather_mean_kernel<<<gridG, 64>>>(image_feats, k_ptr, (float*)d_out, L);
}